// round 5
// baseline (speedup 1.0000x reference)
#include <cuda_runtime.h>

#define NMAX 50000
#define EMAX 850000
#define F 64

// -------- scratch (static device globals; no allocation) --------
__device__ __align__(16) float g_h[NMAX * F];    // h = X @ W for current layer
__device__ __align__(16) float g_acc[NMAX * F];  // layer-1 output / layer-2 GEMM input
__device__ float    g_as[NMAX];    // alpha_src per node
__device__ float    g_ad[NMAX];    // alpha_dst per node
__device__ float    g_ssum[NMAX];  // softmax denominator per dst
__device__ unsigned g_mkey[NMAX];  // softmax max per dst (order-preserving uint key)
__device__ float    g_w[EMAX];     // per-edge scratch: e, then exp(e - m)
__device__ int      g_is64;        // 1 if edge_index is int64, 0 if int32

// order-preserving float <-> uint mapping for atomicMax on floats
__device__ __forceinline__ unsigned f2key(float f) {
    unsigned b = __float_as_uint(f);
    return (b & 0x80000000u) ? ~b : (b | 0x80000000u);
}
__device__ __forceinline__ float key2f(unsigned k) {
    unsigned b = (k & 0x80000000u) ? (k & 0x7fffffffu) : ~k;
    return __uint_as_float(b);
}

// load (src,dst) of logical edge i, honoring detected index dtype
__device__ __forceinline__ void load_edge(const void* ei, int is64, int i, int E,
                                          int Nn, int& s, int& d) {
    if (i >= E) { s = d = i - E; return; }  // self-loops appended after E edges
    if (is64) {
        const long long* p = (const long long*)ei;
        s = (int)p[i];
        d = (int)p[E + i];
    } else {
        const int* p = (const int*)ei;
        s = p[i];
        d = p[E + i];
    }
}

// -------- dtype detection: int64 values must all lie in [0, N) --------
__global__ void detect_k(const long long* __restrict__ ei64, int Nn) {
    if (threadIdx.x == 0 && blockIdx.x == 0) {
        int ok = 1;
        for (int j = 0; j < 8; j++) {
            long long v = ei64[j];
            if (v < 0 || v >= (long long)Nn) ok = 0;
        }
        g_is64 = ok;
    }
}

// -------- init: zero aggregation target, reset max/sum --------
__global__ void init_k(float* __restrict__ out_ext, int use_acc, int Nn) {
    float* acc = use_acc ? g_acc : out_ext;
    int i = blockIdx.x * blockDim.x + threadIdx.x;
    if (i < Nn * F) acc[i] = 0.f;
    if (i < Nn) { g_mkey[i] = 0u; g_ssum[i] = 0.f; }
}

// -------- GEMM: g_h[M,64] = X[M,K] @ W[K,64], fp32 SIMT tiled --------
template <int K>
__global__ void __launch_bounds__(256) gemm64_k(const float* __restrict__ Xext, int use_acc,
                                                const float* __restrict__ W, int M) {
    const float* X = use_acc ? g_acc : Xext;
    __shared__ float sX[16][72];
    __shared__ float sW[16][72];
    const int row0 = blockIdx.x << 6;
    const int t = threadIdx.x;
    const int tr = (t >> 4) << 2;
    const int tc = (t & 15) << 2;
    float acc[4][4];
#pragma unroll
    for (int i = 0; i < 4; i++)
#pragma unroll
        for (int j = 0; j < 4; j++) acc[i][j] = 0.f;

    for (int kb = 0; kb < K; kb += 16) {
        {
            int r = t >> 2;
            int kq = (t & 3) << 2;
            int rg = row0 + r;
            if (rg >= M) rg = M - 1;
            float4 v = *(const float4*)(X + (size_t)rg * K + kb + kq);
            sX[kq + 0][r] = v.x;
            sX[kq + 1][r] = v.y;
            sX[kq + 2][r] = v.z;
            sX[kq + 3][r] = v.w;
        }
#pragma unroll
        for (int j = 0; j < 4; j++) {
            int lin = t + j * 256;
            int k = lin >> 6, c = lin & 63;
            sW[k][c] = W[(size_t)(kb + k) * F + c];
        }
        __syncthreads();
#pragma unroll
        for (int k = 0; k < 16; k++) {
            float4 xv = *(const float4*)&sX[k][tr];
            float4 wv = *(const float4*)&sW[k][tc];
            float xs[4] = {xv.x, xv.y, xv.z, xv.w};
            float ws[4] = {wv.x, wv.y, wv.z, wv.w};
#pragma unroll
            for (int i = 0; i < 4; i++)
#pragma unroll
                for (int j = 0; j < 4; j++) acc[i][j] += xs[i] * ws[j];
        }
        __syncthreads();
    }
#pragma unroll
    for (int i = 0; i < 4; i++) {
        int rg = row0 + tr + i;
        if (rg < M)
            *(float4*)(g_h + (size_t)rg * F + tc) =
                make_float4(acc[i][0], acc[i][1], acc[i][2], acc[i][3]);
    }
}

// -------- per-node attention scalars (warp per node) --------
__global__ void prep_k(const float* __restrict__ av_s, const float* __restrict__ av_d, int Nn) {
    int gt = blockIdx.x * blockDim.x + threadIdx.x;
    int node = gt >> 5, lane = gt & 31;
    if (node >= Nn) return;
    float2 v = ((const float2*)(g_h + (size_t)node * F))[lane];
    float2 a = ((const float2*)av_s)[lane];
    float2 b = ((const float2*)av_d)[lane];
    float s1 = v.x * a.x + v.y * a.y;
    float s2 = v.x * b.x + v.y * b.y;
#pragma unroll
    for (int o = 16; o; o >>= 1) {
        s1 += __shfl_down_sync(0xffffffffu, s1, o);
        s2 += __shfl_down_sync(0xffffffffu, s2, o);
    }
    if (lane == 0) { g_as[node] = s1; g_ad[node] = s2; }
}

// -------- edge pass 1: e = leaky_relu(as[src]+ad[dst]); segment max --------
__global__ void edge_max_k(const void* __restrict__ ei, int E, int Nn) {
    int i = blockIdx.x * blockDim.x + threadIdx.x;
    if (i >= E + Nn) return;
    int is64 = g_is64;
    int s, d;
    load_edge(ei, is64, i, E, Nn, s, d);
    float e = g_as[s] + g_ad[d];
    e = e > 0.f ? e : 0.2f * e;
    g_w[i] = e;
    atomicMax(&g_mkey[d], f2key(e));
}

// -------- edge pass 2: w = exp(e - m[dst]); segment sum --------
__global__ void edge_exp_k(const void* __restrict__ ei, int E, int Nn) {
    int i = blockIdx.x * blockDim.x + threadIdx.x;
    if (i >= E + Nn) return;
    int is64 = g_is64;
    int s, d;
    load_edge(ei, is64, i, E, Nn, s, d);
    float w = __expf(g_w[i] - key2f(g_mkey[d]));
    g_w[i] = w;
    atomicAdd(&g_ssum[d], w);
}

// -------- edge pass 3: out[dst] += (w/denom[dst]) * h[src], 16 threads/edge --------
__global__ void scatter_k(const void* __restrict__ ei, float* __restrict__ out_ext,
                          int use_acc, int E, int Nn) {
    float* out = use_acc ? g_acc : out_ext;
    long long t = (long long)blockIdx.x * blockDim.x + threadIdx.x;
    int i = (int)(t >> 4);
    if (i >= E + Nn) return;
    int c = ((int)t & 15) << 2;
    int is64 = g_is64;
    int s, d;
    load_edge(ei, is64, i, E, Nn, s, d);
    float alpha = g_w[i] / (g_ssum[d] + 1e-16f);
    float4 v = *(const float4*)(g_h + (size_t)s * F + c);
    float* p = out + (size_t)d * F + c;
    atomicAdd(p + 0, alpha * v.x);
    atomicAdd(p + 1, alpha * v.y);
    atomicAdd(p + 2, alpha * v.z);
    atomicAdd(p + 3, alpha * v.w);
}

// -------- finalize: add bias (+ optional relu) --------
__global__ void finalize_k(float* __restrict__ out_ext, int use_acc,
                           const float* __restrict__ b, int Nn, int do_relu) {
    float* out = use_acc ? g_acc : out_ext;
    int i = blockIdx.x * blockDim.x + threadIdx.x;
    if (i >= Nn * F) return;
    float v = out[i] + b[i & (F - 1)];
    if (do_relu) v = fmaxf(v, 0.f);
    out[i] = v;
}

static inline int cdiv(int a, int b) { return (a + b - 1) / b; }

extern "C" void kernel_launch(void* const* d_in, const int* in_sizes, int n_in,
                              void* d_out, int out_size) {
    const float* x   = (const float*)d_in[0];
    const void*  ei  = d_in[1];
    const float* W1  = (const float*)d_in[2];
    const float* a1s = (const float*)d_in[3];
    const float* a1d = (const float*)d_in[4];
    const float* b1  = (const float*)d_in[5];
    const float* W2  = (const float*)d_in[6];
    const float* a2s = (const float*)d_in[7];
    const float* a2d = (const float*)d_in[8];
    const float* b2  = (const float*)d_in[9];
    float* out = (float*)d_out;

    const int N = in_sizes[0] / 128;  // 50000
    const int E = in_sizes[1] / 2;    // 800000 (element count is dtype-agnostic)
    const int T = E + N;

    const int thr = 256;
    const int gNF = cdiv(N * F, thr);
    const int gPrep = cdiv(N * 32, thr);
    const int gE = cdiv(T, thr);
    const int gScat = (int)(((long long)T * 16 + thr - 1) / thr);

    detect_k<<<1, 32>>>((const long long*)ei, N);

    // ---- layer 1 (aggregate into g_acc) ----
    init_k<<<gNF, thr>>>(out, 1, N);
    gemm64_k<128><<<cdiv(N, 64), thr>>>(x, 0, W1, N);
    prep_k<<<gPrep, thr>>>(a1s, a1d, N);
    edge_max_k<<<gE, thr>>>(ei, E, N);
    edge_exp_k<<<gE, thr>>>(ei, E, N);
    scatter_k<<<gScat, thr>>>(ei, out, 1, E, N);
    finalize_k<<<gNF, thr>>>(out, 1, b1, N, 1);  // g_acc += b1, relu

    // ---- layer 2 (aggregate into d_out) ----
    init_k<<<gNF, thr>>>(out, 0, N);
    gemm64_k<64><<<cdiv(N, 64), thr>>>(nullptr, 1, W2, N);
    prep_k<<<gPrep, thr>>>(a2s, a2d, N);
    edge_max_k<<<gE, thr>>>(ei, E, N);
    edge_exp_k<<<gE, thr>>>(ei, E, N);
    scatter_k<<<gScat, thr>>>(ei, out, 0, E, N);
    finalize_k<<<gNF, thr>>>(out, 0, b2, N, 0);  // d_out += b2
}

// round 6
// speedup vs baseline: 1.6530x; 1.6530x over previous
#include <cuda_runtime.h>

#define NMAX 50000
#define EMAX 850000
#define F 64

// -------- scratch (static device globals; no allocation) --------
__device__ __align__(16) float g_h[NMAX * F];    // h = X @ W for current layer
__device__ __align__(16) float g_acc[NMAX * F];  // layer-1 output / layer-2 GEMM input
__device__ float g_as[NMAX];          // alpha_src per node
__device__ float g_ad[NMAX];          // alpha_dst per node
__device__ int   g_deg[NMAX];         // in-degree histogram
__device__ int   g_rowptr[NMAX + 1];  // CSR row pointers (by dst)
__device__ int   g_cursor[NMAX];      // fill cursors
__device__ int   g_esrc[EMAX];        // CSR payload: src node of each incoming edge
__device__ int   g_is64;              // 1 if edge_index is int64, 0 if int32

// load (src,dst) of logical edge i, honoring detected index dtype
__device__ __forceinline__ void load_edge(const void* ei, int is64, int i, int E,
                                          int& s, int& d) {
    if (i >= E) { s = d = i - E; return; }  // self-loops appended after E edges
    if (is64) {
        const long long* p = (const long long*)ei;
        s = (int)p[i];
        d = (int)p[E + i];
    } else {
        const int* p = (const int*)ei;
        s = p[i];
        d = p[E + i];
    }
}

// -------- dtype detection: int64 values must all lie in [0, N) --------
__global__ void detect_k(const long long* __restrict__ ei64, int Nn) {
    if (threadIdx.x == 0 && blockIdx.x == 0) {
        int ok = 1;
        for (int j = 0; j < 8; j++) {
            long long v = ei64[j];
            if (v < 0 || v >= (long long)Nn) ok = 0;
        }
        g_is64 = ok;
    }
}

// -------- CSR build --------
__global__ void zero_deg_k(int Nn) {
    int i = blockIdx.x * blockDim.x + threadIdx.x;
    if (i < Nn) g_deg[i] = 0;
}

__global__ void hist_k(const void* __restrict__ ei, int E, int Nn) {
    int i = blockIdx.x * blockDim.x + threadIdx.x;
    if (i >= E + Nn) return;
    int s, d;
    load_edge(ei, g_is64, i, E, s, d);
    atomicAdd(&g_deg[d], 1);
}

// single-block exclusive scan over g_deg -> g_rowptr / g_cursor
__global__ void __launch_bounds__(1024) scan_k(int Nn) {
    __shared__ int sh[1024];
    int t = threadIdx.x;
    int chunk = (Nn + 1023) >> 10;
    int start = t * chunk;
    int end = start + chunk;
    if (start > Nn) start = Nn;
    if (end > Nn) end = Nn;
    int s = 0;
    for (int i = start; i < end; i++) s += g_deg[i];
    sh[t] = s;
    __syncthreads();
    // inclusive Hillis-Steele scan
    for (int o = 1; o < 1024; o <<= 1) {
        int v = (t >= o) ? sh[t - o] : 0;
        __syncthreads();
        sh[t] += v;
        __syncthreads();
    }
    int off = (t > 0) ? sh[t - 1] : 0;
    for (int i = start; i < end; i++) {
        g_rowptr[i] = off;
        g_cursor[i] = off;
        off += g_deg[i];
    }
    if (t == 1023) g_rowptr[Nn] = sh[1023];
}

__global__ void fill_k(const void* __restrict__ ei, int E, int Nn) {
    int i = blockIdx.x * blockDim.x + threadIdx.x;
    if (i >= E + Nn) return;
    int s, d;
    load_edge(ei, g_is64, i, E, s, d);
    int pos = atomicAdd(&g_cursor[d], 1);
    g_esrc[pos] = s;
}

// -------- GEMM: g_h[M,64] = X[M,K] @ W[K,64], fp32 SIMT tiled --------
template <int K>
__global__ void __launch_bounds__(256) gemm64_k(const float* __restrict__ Xext, int use_acc,
                                                const float* __restrict__ W, int M) {
    const float* X = use_acc ? g_acc : Xext;
    __shared__ float sX[16][72];
    __shared__ float sW[16][72];
    const int row0 = blockIdx.x << 6;
    const int t = threadIdx.x;
    const int tr = (t >> 4) << 2;
    const int tc = (t & 15) << 2;
    float acc[4][4];
#pragma unroll
    for (int i = 0; i < 4; i++)
#pragma unroll
        for (int j = 0; j < 4; j++) acc[i][j] = 0.f;

    for (int kb = 0; kb < K; kb += 16) {
        {
            int r = t >> 2;
            int kq = (t & 3) << 2;
            int rg = row0 + r;
            if (rg >= M) rg = M - 1;
            float4 v = *(const float4*)(X + (size_t)rg * K + kb + kq);
            sX[kq + 0][r] = v.x;
            sX[kq + 1][r] = v.y;
            sX[kq + 2][r] = v.z;
            sX[kq + 3][r] = v.w;
        }
#pragma unroll
        for (int j = 0; j < 4; j++) {
            int lin = t + j * 256;
            int k = lin >> 6, c = lin & 63;
            sW[k][c] = W[(size_t)(kb + k) * F + c];
        }
        __syncthreads();
#pragma unroll
        for (int k = 0; k < 16; k++) {
            float4 xv = *(const float4*)&sX[k][tr];
            float4 wv = *(const float4*)&sW[k][tc];
            float xs[4] = {xv.x, xv.y, xv.z, xv.w};
            float ws[4] = {wv.x, wv.y, wv.z, wv.w};
#pragma unroll
            for (int i = 0; i < 4; i++)
#pragma unroll
                for (int j = 0; j < 4; j++) acc[i][j] += xs[i] * ws[j];
        }
        __syncthreads();
    }
#pragma unroll
    for (int i = 0; i < 4; i++) {
        int rg = row0 + tr + i;
        if (rg < M)
            *(float4*)(g_h + (size_t)rg * F + tc) =
                make_float4(acc[i][0], acc[i][1], acc[i][2], acc[i][3]);
    }
}

// -------- per-node attention scalars (warp per node) --------
__global__ void prep_k(const float* __restrict__ av_s, const float* __restrict__ av_d, int Nn) {
    int gt = blockIdx.x * blockDim.x + threadIdx.x;
    int node = gt >> 5, lane = gt & 31;
    if (node >= Nn) return;
    float2 v = ((const float2*)(g_h + (size_t)node * F))[lane];
    float2 a = ((const float2*)av_s)[lane];
    float2 b = ((const float2*)av_d)[lane];
    float s1 = v.x * a.x + v.y * a.y;
    float s2 = v.x * b.x + v.y * b.y;
#pragma unroll
    for (int o = 16; o; o >>= 1) {
        s1 += __shfl_down_sync(0xffffffffu, s1, o);
        s2 += __shfl_down_sync(0xffffffffu, s2, o);
    }
    if (lane == 0) { g_as[node] = s1; g_ad[node] = s2; }
}

// -------- fused aggregation: warp per dst node, gather over CSR --------
// out[dst] = sum_e alpha_e * h[src_e] + bias   (+ optional relu)
__global__ void agg_k(float* __restrict__ out_ext, int use_acc,
                      const float* __restrict__ bias, int do_relu, int Nn) {
    float* out = use_acc ? g_acc : out_ext;
    int gt = blockIdx.x * blockDim.x + threadIdx.x;
    int node = gt >> 5, lane = gt & 31;
    if (node >= Nn) return;
    const int beg = g_rowptr[node];
    const int end = g_rowptr[node + 1];
    const float adv = g_ad[node];

    // segment max
    float m = -3.4e38f;
    for (int j = beg + lane; j < end; j += 32) {
        float e = g_as[g_esrc[j]] + adv;
        e = e > 0.f ? e : 0.2f * e;
        m = fmaxf(m, e);
    }
#pragma unroll
    for (int o = 16; o; o >>= 1) m = fmaxf(m, __shfl_xor_sync(0xffffffffu, m, o));

    // segment sum of exp(e - m)
    float sum = 0.f;
    for (int j = beg + lane; j < end; j += 32) {
        float e = g_as[g_esrc[j]] + adv;
        e = e > 0.f ? e : 0.2f * e;
        sum += __expf(e - m);
    }
#pragma unroll
    for (int o = 16; o; o >>= 1) sum += __shfl_xor_sync(0xffffffffu, sum, o);
    const float inv = 1.f / (sum + 1e-16f);

    // weighted feature accumulation: all 32 lanes cover the 64-float row
    float2 acc = make_float2(0.f, 0.f);
    for (int j = beg; j < end; j++) {
        int s = g_esrc[j];  // uniform across warp -> broadcast load
        float e = g_as[s] + adv;
        e = e > 0.f ? e : 0.2f * e;
        float alpha = __expf(e - m) * inv;
        float2 v = *(const float2*)(g_h + (size_t)s * F + lane * 2);
        acc.x += alpha * v.x;
        acc.y += alpha * v.y;
    }
    float2 bv = ((const float2*)bias)[lane];
    acc.x += bv.x;
    acc.y += bv.y;
    if (do_relu) { acc.x = fmaxf(acc.x, 0.f); acc.y = fmaxf(acc.y, 0.f); }
    *(float2*)(out + (size_t)node * F + lane * 2) = acc;
}

static inline int cdiv(int a, int b) { return (a + b - 1) / b; }

extern "C" void kernel_launch(void* const* d_in, const int* in_sizes, int n_in,
                              void* d_out, int out_size) {
    const float* x   = (const float*)d_in[0];
    const void*  ei  = d_in[1];
    const float* W1  = (const float*)d_in[2];
    const float* a1s = (const float*)d_in[3];
    const float* a1d = (const float*)d_in[4];
    const float* b1  = (const float*)d_in[5];
    const float* W2  = (const float*)d_in[6];
    const float* a2s = (const float*)d_in[7];
    const float* a2d = (const float*)d_in[8];
    const float* b2  = (const float*)d_in[9];
    float* out = (float*)d_out;

    const int N = in_sizes[0] / 128;  // 50000
    const int E = in_sizes[1] / 2;    // 800000
    const int T = E + N;

    const int thr = 256;
    const int gN = cdiv(N, thr);
    const int gPrep = cdiv(N * 32, thr);
    const int gE = cdiv(T, thr);

    // dtype + CSR build (shared by both layers)
    detect_k<<<1, 32>>>((const long long*)ei, N);
    zero_deg_k<<<gN, thr>>>(N);
    hist_k<<<gE, thr>>>(ei, E, N);
    scan_k<<<1, 1024>>>(N);
    fill_k<<<gE, thr>>>(ei, E, N);

    // ---- layer 1 -> g_acc (bias + relu fused) ----
    gemm64_k<128><<<cdiv(N, 64), thr>>>(x, 0, W1, N);
    prep_k<<<gPrep, thr>>>(a1s, a1d, N);
    agg_k<<<gPrep, thr>>>(out, 1, b1, 1, N);

    // ---- layer 2 -> d_out (bias fused) ----
    gemm64_k<64><<<cdiv(N, 64), thr>>>(nullptr, 1, W2, N);
    prep_k<<<gPrep, thr>>>(a2s, a2d, N);
    agg_k<<<gPrep, thr>>>(out, 0, b2, 0, N);
}

// round 8
// speedup vs baseline: 2.6052x; 1.5760x over previous
#include <cuda_runtime.h>

#define NMAX 50000
#define EMAX 850000
#define F 64

// -------- scratch (static device globals; no allocation) --------
__device__ __align__(16) float g_h[NMAX * F];    // h = X @ W for current layer
__device__ __align__(16) float g_acc[NMAX * F];  // layer-1 output / layer-2 GEMM input
__device__ float g_as[NMAX];          // alpha_src per node
__device__ float g_ad[NMAX];          // alpha_dst per node
__device__ int   g_deg[NMAX];         // in-degree histogram
__device__ int   g_rowptr[NMAX + 1];  // CSR row pointers (by dst)
__device__ int   g_cursor[NMAX];      // fill cursors
__device__ int   g_esrc[EMAX];        // CSR payload: src node of each incoming edge
__device__ float g_w[EMAX];           // per-edge exp(e-m) cache (CSR order)
__device__ int   g_bsum[64];          // per-block scan partial sums
__device__ int   g_boff[64];          // per-block scan offsets
__device__ int   g_is64;              // 1 if edge_index is int64, 0 if int32

// load (src,dst) of logical edge i, honoring detected index dtype
__device__ __forceinline__ void load_edge(const void* ei, int is64, int i, int E,
                                          int& s, int& d) {
    if (i >= E) { s = d = i - E; return; }  // self-loops appended after E edges
    if (is64) {
        const long long* p = (const long long*)ei;
        s = (int)p[i];
        d = (int)p[E + i];
    } else {
        const int* p = (const int*)ei;
        s = p[i];
        d = p[E + i];
    }
}

// -------- dtype detection: int64 values must all lie in [0, N) --------
__global__ void detect_k(const long long* __restrict__ ei64, int Nn) {
    if (threadIdx.x == 0 && blockIdx.x == 0) {
        int ok = 1;
        for (int j = 0; j < 8; j++) {
            long long v = ei64[j];
            if (v < 0 || v >= (long long)Nn) ok = 0;
        }
        g_is64 = ok;
    }
}

// -------- CSR build --------
__global__ void zero_deg_k(int Nn) {
    int i = blockIdx.x * blockDim.x + threadIdx.x;
    if (i < Nn) g_deg[i] = 0;
}

__global__ void hist_k(const void* __restrict__ ei, int E, int Nn) {
    int i = blockIdx.x * blockDim.x + threadIdx.x;
    if (i >= E + Nn) return;
    int s, d;
    load_edge(ei, g_is64, i, E, s, d);
    atomicAdd(&g_deg[d], 1);
}

// phase 1: per-block exclusive scan of g_deg (1024 elts/block) + block sums
__global__ void __launch_bounds__(1024) scan1_k(int Nn) {
    __shared__ int sh[1024];
    int t = threadIdx.x;
    int i = blockIdx.x * 1024 + t;
    int v = (i < Nn) ? g_deg[i] : 0;
    sh[t] = v;
    __syncthreads();
#pragma unroll
    for (int o = 1; o < 1024; o <<= 1) {
        int u = (t >= o) ? sh[t - o] : 0;
        __syncthreads();
        sh[t] += u;
        __syncthreads();
    }
    if (i < Nn) g_rowptr[i] = sh[t] - v;  // exclusive within block
    if (t == 1023) g_bsum[blockIdx.x] = sh[1023];
}

// phase 2: serial exclusive scan of block sums (<=64 of them)
__global__ void scan2_k(int nb) {
    if (threadIdx.x == 0) {
        int acc = 0;
        for (int b = 0; b < nb; b++) {
            g_boff[b] = acc;
            acc += g_bsum[b];
        }
    }
}

// phase 3: apply block offsets; rowptr[N] = E + N (known total)
__global__ void __launch_bounds__(1024) scan3_k(int Nn, int total) {
    int i = blockIdx.x * 1024 + threadIdx.x;
    if (i < Nn) {
        int r = g_rowptr[i] + g_boff[blockIdx.x];
        g_rowptr[i] = r;
        g_cursor[i] = r;
    }
    if (i == Nn) g_rowptr[Nn] = total;
}

__global__ void fill_k(const void* __restrict__ ei, int E, int Nn) {
    int i = blockIdx.x * blockDim.x + threadIdx.x;
    if (i >= E + Nn) return;
    int s, d;
    load_edge(ei, g_is64, i, E, s, d);
    int pos = atomicAdd(&g_cursor[d], 1);
    g_esrc[pos] = s;
}

// -------- GEMM: g_h[M,64] = X[M,K] @ W[K,64], fp32 SIMT tiled --------
template <int K>
__global__ void __launch_bounds__(256) gemm64_k(const float* __restrict__ Xext, int use_acc,
                                                const float* __restrict__ W, int M) {
    const float* X = use_acc ? g_acc : Xext;
    __shared__ float sX[16][72];
    __shared__ float sW[16][72];
    const int row0 = blockIdx.x << 6;
    const int t = threadIdx.x;
    const int tr = (t >> 4) << 2;
    const int tc = (t & 15) << 2;
    float acc[4][4];
#pragma unroll
    for (int i = 0; i < 4; i++)
#pragma unroll
        for (int j = 0; j < 4; j++) acc[i][j] = 0.f;

    for (int kb = 0; kb < K; kb += 16) {
        {
            int r = t >> 2;
            int kq = (t & 3) << 2;
            int rg = row0 + r;
            if (rg >= M) rg = M - 1;
            float4 v = *(const float4*)(X + (size_t)rg * K + kb + kq);
            sX[kq + 0][r] = v.x;
            sX[kq + 1][r] = v.y;
            sX[kq + 2][r] = v.z;
            sX[kq + 3][r] = v.w;
        }
#pragma unroll
        for (int j = 0; j < 4; j++) {
            int lin = t + j * 256;
            int k = lin >> 6, c = lin & 63;
            sW[k][c] = W[(size_t)(kb + k) * F + c];
        }
        __syncthreads();
#pragma unroll
        for (int k = 0; k < 16; k++) {
            float4 xv = *(const float4*)&sX[k][tr];
            float4 wv = *(const float4*)&sW[k][tc];
            float xs[4] = {xv.x, xv.y, xv.z, xv.w};
            float ws[4] = {wv.x, wv.y, wv.z, wv.w};
#pragma unroll
            for (int i = 0; i < 4; i++)
#pragma unroll
                for (int j = 0; j < 4; j++) acc[i][j] += xs[i] * ws[j];
        }
        __syncthreads();
    }
#pragma unroll
    for (int i = 0; i < 4; i++) {
        int rg = row0 + tr + i;
        if (rg < M)
            *(float4*)(g_h + (size_t)rg * F + tc) =
                make_float4(acc[i][0], acc[i][1], acc[i][2], acc[i][3]);
    }
}

// -------- per-node attention scalars (warp per node) --------
__global__ void prep_k(const float* __restrict__ av_s, const float* __restrict__ av_d, int Nn) {
    int gt = blockIdx.x * blockDim.x + threadIdx.x;
    int node = gt >> 5, lane = gt & 31;
    if (node >= Nn) return;
    float2 v = ((const float2*)(g_h + (size_t)node * F))[lane];
    float2 a = ((const float2*)av_s)[lane];
    float2 b = ((const float2*)av_d)[lane];
    float s1 = v.x * a.x + v.y * a.y;
    float s2 = v.x * b.x + v.y * b.y;
#pragma unroll
    for (int o = 16; o; o >>= 1) {
        s1 += __shfl_down_sync(0xffffffffu, s1, o);
        s2 += __shfl_down_sync(0xffffffffu, s2, o);
    }
    if (lane == 0) { g_as[node] = s1; g_ad[node] = s2; }
}

// -------- fused aggregation: warp per dst node, gather over CSR --------
// out[dst] = sum_e alpha_e * h[src_e] + bias   (+ optional relu)
__global__ void agg_k(float* __restrict__ out_ext, int use_acc,
                      const float* __restrict__ bias, int do_relu, int Nn) {
    float* out = use_acc ? g_acc : out_ext;
    int gt = blockIdx.x * blockDim.x + threadIdx.x;
    int node = gt >> 5, lane = gt & 31;
    if (node >= Nn) return;
    const int beg = g_rowptr[node];
    const int end = g_rowptr[node + 1];
    const float adv = g_ad[node];

    // segment max
    float m = -3.4e38f;
    for (int j = beg + lane; j < end; j += 32) {
        float e = g_as[g_esrc[j]] + adv;
        e = e > 0.f ? e : 0.2f * e;
        m = fmaxf(m, e);
    }
#pragma unroll
    for (int o = 16; o; o >>= 1) m = fmaxf(m, __shfl_xor_sync(0xffffffffu, m, o));

    // segment sum of exp(e - m); cache exp into g_w (CSR order, this node's slice)
    float sum = 0.f;
    for (int j = beg + lane; j < end; j += 32) {
        float e = g_as[g_esrc[j]] + adv;
        e = e > 0.f ? e : 0.2f * e;
        float w = __expf(e - m);
        g_w[j] = w;
        sum += w;
    }
#pragma unroll
    for (int o = 16; o; o >>= 1) sum += __shfl_xor_sync(0xffffffffu, sum, o);
    const float inv = 1.f / (sum + 1e-16f);

    // weighted feature accumulation: all 32 lanes cover the 64-float row
    float2 acc = make_float2(0.f, 0.f);
    for (int j = beg; j < end; j++) {
        int s = g_esrc[j];                 // uniform across warp -> broadcast load
        float alpha = g_w[j] * inv;        // broadcast load of cached exp
        float2 v = *(const float2*)(g_h + (size_t)s * F + lane * 2);
        acc.x += alpha * v.x;
        acc.y += alpha * v.y;
    }
    float2 bv = ((const float2*)bias)[lane];
    acc.x += bv.x;
    acc.y += bv.y;
    if (do_relu) { acc.x = fmaxf(acc.x, 0.f); acc.y = fmaxf(acc.y, 0.f); }
    *(float2*)(out + (size_t)node * F + lane * 2) = acc;
}

static inline int cdiv(int a, int b) { return (a + b - 1) / b; }

extern "C" void kernel_launch(void* const* d_in, const int* in_sizes, int n_in,
                              void* d_out, int out_size) {
    const float* x   = (const float*)d_in[0];
    const void*  ei  = d_in[1];
    const float* W1  = (const float*)d_in[2];
    const float* a1s = (const float*)d_in[3];
    const float* a1d = (const float*)d_in[4];
    const float* b1  = (const float*)d_in[5];
    const float* W2  = (const float*)d_in[6];
    const float* a2s = (const float*)d_in[7];
    const float* a2d = (const float*)d_in[8];
    const float* b2  = (const float*)d_in[9];
    float* out = (float*)d_out;

    const int N = in_sizes[0] / 128;  // 50000
    const int E = in_sizes[1] / 2;    // 800000
    const int T = E + N;

    const int thr = 256;
    const int gN = cdiv(N, thr);
    const int gPrep = cdiv(N * 32, thr);
    const int gE = cdiv(T, thr);
    const int nScanBlk = cdiv(N, 1024);

    // dtype + CSR build (shared by both layers)
    detect_k<<<1, 32>>>((const long long*)ei, N);
    zero_deg_k<<<gN, thr>>>(N);
    hist_k<<<gE, thr>>>(ei, E, N);
    scan1_k<<<nScanBlk, 1024>>>(N);
    scan2_k<<<1, 32>>>(nScanBlk);
    scan3_k<<<nScanBlk + 1, 1024>>>(N, T);  // +1 block covers i == N
    fill_k<<<gE, thr>>>(ei, E, N);

    // ---- layer 1 -> g_acc (bias + relu fused) ----
    gemm64_k<128><<<cdiv(N, 64), thr>>>(x, 0, W1, N);
    prep_k<<<gPrep, thr>>>(a1s, a1d, N);
    agg_k<<<gPrep, thr>>>(out, 1, b1, 1, N);

    // ---- layer 2 -> d_out (bias fused) ----
    gemm64_k<64><<<cdiv(N, 64), thr>>>(nullptr, 1, W2, N);
    prep_k<<<gPrep, thr>>>(a2s, a2d, N);
    agg_k<<<gPrep, thr>>>(out, 0, b2, 0, N);
}